// round 3
// baseline (speedup 1.0000x reference)
#include <cuda_runtime.h>
#include <cstdint>

#define NN 100000
#define EE 1600000
#define NODE_DIM 128
#define HC 32          // heads * channels
#define NHEAD 2
#define NEG_SLOPE 0.2f

// ---------------- scratch (device globals; no allocations allowed) ----------
__device__ float g_xl[NN * HC];
__device__ float g_xr[NN * HC];
__device__ float g_num[NN * HC];
__device__ float g_h[NN * HC];
__device__ float g_den[NN * NHEAD];
__device__ float g_loop[NN];
__device__ float g_deg[NN];
__device__ float g_lsum[NN];

// ---------------- degree / self-loop edge_attr ------------------------------
__global__ void zero_deg_kernel() {
    int i = blockIdx.x * blockDim.x + threadIdx.x;
    if (i < NN) { g_deg[i] = 0.f; g_lsum[i] = 0.f; }
}

__global__ void deg_kernel(const int* __restrict__ dst,
                           const float* __restrict__ eattr) {
    int e = blockIdx.x * blockDim.x + threadIdx.x;
    if (e < EE) {
        int d = dst[e];
        atomicAdd(&g_deg[d], 1.f);
        atomicAdd(&g_lsum[d], eattr[e]);
    }
}

__global__ void loop_kernel() {
    int i = blockIdx.x * blockDim.x + threadIdx.x;
    if (i < NN) g_loop[i] = g_lsum[i] / fmaxf(g_deg[i], 1.f);
}

// ---------------- linear projections: warp per node -------------------------
// xl = in @ Wl + bl ; xr = in @ Wr + br    (W: [D, 32] row-major)
// USE_GH=0: input is the kernel argument x (layer 1, D=128)
// USE_GH=1: input is the device-global g_h (layer 2, D=32) — a __device__
//           symbol must be referenced from DEVICE code, never passed from host.
template <int D, int USE_GH>
__global__ void __launch_bounds__(256) proj_kernel(
    const float* __restrict__ x,
    const float* __restrict__ Wl, const float* __restrict__ bl,
    const float* __restrict__ Wr, const float* __restrict__ br)
{
    int warp = (blockIdx.x * blockDim.x + threadIdx.x) >> 5;
    int lane = threadIdx.x & 31;
    if (warp >= NN) return;
    const float* in = USE_GH ? (const float*)g_h : x;
    const float* xrow = in + (size_t)warp * D;
    float al = __ldg(bl + lane);
    float ar = __ldg(br + lane);
#pragma unroll 8
    for (int k = 0; k < D; k += 4) {
        float4 xv = *(const float4*)(xrow + k);
        al += xv.x * __ldg(Wl + (k + 0) * HC + lane);
        ar += xv.x * __ldg(Wr + (k + 0) * HC + lane);
        al += xv.y * __ldg(Wl + (k + 1) * HC + lane);
        ar += xv.y * __ldg(Wr + (k + 1) * HC + lane);
        al += xv.z * __ldg(Wl + (k + 2) * HC + lane);
        ar += xv.z * __ldg(Wr + (k + 2) * HC + lane);
        al += xv.w * __ldg(Wl + (k + 3) * HC + lane);
        ar += xv.w * __ldg(Wr + (k + 3) * HC + lane);
    }
    g_xl[warp * HC + lane] = al;
    g_xr[warp * HC + lane] = ar;
}

__device__ __forceinline__ float half_reduce16(float t) {
    // sum over 16-lane half-warp (lanes 0-15 and 16-31 independently)
    t += __shfl_xor_sync(0xffffffffu, t, 1);
    t += __shfl_xor_sync(0xffffffffu, t, 2);
    t += __shfl_xor_sync(0xffffffffu, t, 4);
    t += __shfl_xor_sync(0xffffffffu, t, 8);
    return t;
}

// ---------------- self-loop init: num = a_self * xl, den = a_self -----------
__global__ void __launch_bounds__(256) selfinit_kernel(
    const float* __restrict__ We, const float* __restrict__ att)
{
    int n = (blockIdx.x * blockDim.x + threadIdx.x) >> 5;
    int lane = threadIdx.x & 31;
    if (n >= NN) return;
    float xlv = g_xl[n * HC + lane];
    float v = xlv + g_xr[n * HC + lane] + g_loop[n] * __ldg(We + lane);
    v = (v >= 0.f) ? v : NEG_SLOPE * v;
    float t = half_reduce16(v * __ldg(att + lane));   // logit for this head
    float a = __expf(t);
    g_num[n * HC + lane] = a * xlv;
    if ((lane & 15) == 0) g_den[n * NHEAD + (lane >> 4)] = a;
}

// ---------------- edge pass: warp per edge ----------------------------------
__global__ void __launch_bounds__(256) edge_kernel(
    const int* __restrict__ src, const int* __restrict__ dst,
    const float* __restrict__ eattr,
    const float* __restrict__ We, const float* __restrict__ att)
{
    int e = (blockIdx.x * blockDim.x + threadIdx.x) >> 5;
    int lane = threadIdx.x & 31;
    if (e >= EE) return;
    int s = __ldg(src + e);
    int d = __ldg(dst + e);
    float ea = __ldg(eattr + e);
    float xlv = __ldg(&g_xl[s * HC + lane]);          // coalesced 128B line
    float v = xlv + __ldg(&g_xr[d * HC + lane]) + ea * __ldg(We + lane);
    v = (v >= 0.f) ? v : NEG_SLOPE * v;
    float t = half_reduce16(v * __ldg(att + lane));   // per-head logit
    float a = __expf(t);
    atomicAdd(&g_num[d * HC + lane], a * xlv);
    if ((lane & 15) == 0) atomicAdd(&g_den[d * NHEAD + (lane >> 4)], a);
}

// ---------------- finalize: h = num / den + bias ----------------------------
__global__ void __launch_bounds__(256) finalize_kernel(const float* __restrict__ bias)
{
    int i = blockIdx.x * blockDim.x + threadIdx.x;
    if (i >= NN * HC) return;
    int n = i >> 5;
    int l = i & 31;
    g_h[i] = g_num[i] / g_den[n * NHEAD + (l >> 4)] + __ldg(bias + l);
}

// ---------------- decoder: warp per node ------------------------------------
__global__ void __launch_bounds__(256) decoder_kernel(
    const float* __restrict__ Wd1, const float* __restrict__ bd1,
    const float* __restrict__ Wd2, const float* __restrict__ bd2,
    float* __restrict__ out)
{
    int n = (blockIdx.x * blockDim.x + threadIdx.x) >> 5;
    int lane = threadIdx.x & 31;
    if (n >= NN) return;
    float myh = g_h[n * HC + lane];
    float hid = __ldg(bd1 + lane);
#pragma unroll
    for (int k = 0; k < HC; k++) {
        float hv = __shfl_sync(0xffffffffu, myh, k);
        hid += hv * __ldg(Wd1 + k * HC + lane);
    }
    hid = fmaxf(hid, 0.f);
    float o0 = hid * __ldg(Wd2 + lane * 2 + 0);
    float o1 = hid * __ldg(Wd2 + lane * 2 + 1);
#pragma unroll
    for (int m = 16; m > 0; m >>= 1) {
        o0 += __shfl_xor_sync(0xffffffffu, o0, m);
        o1 += __shfl_xor_sync(0xffffffffu, o1, m);
    }
    if (lane == 0) {
        out[n * 2 + 0] = o0 + __ldg(bd2 + 0);
        out[n * 2 + 1] = o1 + __ldg(bd2 + 1);
    }
}

// ---------------- launch ----------------------------------------------------
extern "C" void kernel_launch(void* const* d_in, const int* in_sizes, int n_in,
                              void* d_out, int out_size)
{
    const float* x    = (const float*)d_in[0];
    const int*   ei   = (const int*)  d_in[1];
    const float* ea   = (const float*)d_in[2];
    const float* Wl1  = (const float*)d_in[3];
    const float* bl1  = (const float*)d_in[4];
    const float* Wr1  = (const float*)d_in[5];
    const float* br1  = (const float*)d_in[6];
    const float* We1  = (const float*)d_in[7];
    const float* att1 = (const float*)d_in[8];
    const float* b1   = (const float*)d_in[9];
    const float* Wl2  = (const float*)d_in[10];
    const float* bl2  = (const float*)d_in[11];
    const float* Wr2  = (const float*)d_in[12];
    const float* br2  = (const float*)d_in[13];
    const float* We2  = (const float*)d_in[14];
    const float* att2 = (const float*)d_in[15];
    const float* b2   = (const float*)d_in[16];
    const float* Wd1  = (const float*)d_in[17];
    const float* bd1  = (const float*)d_in[18];
    const float* Wd2  = (const float*)d_in[19];
    const float* bd2  = (const float*)d_in[20];
    float* out = (float*)d_out;

    const int* src = ei;
    const int* dst = ei + EE;

    const int TB = 256;
    int nodeBlocks  = (NN + TB - 1) / TB;           // thread-per-node grids
    int nodeWarpBlk = (NN * 32 + TB - 1) / TB;      // warp-per-node grids
    int edgeBlocks  = (EE + TB - 1) / TB;           // thread-per-edge grids
    int edgeWarpBlk = (EE * 32 + TB - 1) / TB;      // warp-per-edge grids
    int ncBlocks    = (NN * HC + TB - 1) / TB;      // thread-per-(node,col)

    // self-loop attr (shared by both layers)
    zero_deg_kernel<<<nodeBlocks, TB>>>();
    deg_kernel<<<edgeBlocks, TB>>>(dst, ea);
    loop_kernel<<<nodeBlocks, TB>>>();

    // ---- layer 1 ----
    proj_kernel<NODE_DIM, 0><<<nodeWarpBlk, TB>>>(x, Wl1, bl1, Wr1, br1);
    selfinit_kernel<<<nodeWarpBlk, TB>>>(We1, att1);
    edge_kernel<<<edgeWarpBlk, TB>>>(src, dst, ea, We1, att1);
    finalize_kernel<<<ncBlocks, TB>>>(b1);          // -> g_h

    // ---- layer 2 (input g_h read inside the kernel, D=32) ----
    proj_kernel<HC, 1><<<nodeWarpBlk, TB>>>(nullptr, Wl2, bl2, Wr2, br2);
    selfinit_kernel<<<nodeWarpBlk, TB>>>(We2, att2);
    edge_kernel<<<edgeWarpBlk, TB>>>(src, dst, ea, We2, att2);
    finalize_kernel<<<ncBlocks, TB>>>(b2);          // -> g_h (reused)

    // ---- decoder ----
    decoder_kernel<<<nodeWarpBlk, TB>>>(Wd1, bd1, Wd2, bd2, out);
}